// round 1
// baseline (speedup 1.0000x reference)
#include <cuda_runtime.h>
#include <cuda_bf16.h>
#include <math.h>

#define B_ 2
#define S_ 2048
#define D_ 2048
#define NH_ 32
#define NKV_ 8
#define HD_ 64
#define M_ (B_ * S_)            // 4096
#define QCOLS (NH_ * HD_)       // 2048
#define KCOLS (NKV_ * HD_)      // 512

// ---------------- scratch (device globals; no allocations allowed) ----------
__device__ float g_q[M_ * QCOLS];   // 33.5 MB
__device__ float g_k[M_ * KCOLS];   //  8.4 MB
__device__ float g_v[M_ * KCOLS];   //  8.4 MB
__device__ float g_ao[M_ * QCOLS];  // 33.5 MB

// ---------------- SGEMM: C[M,N] = A[M,K] @ B[K,N], fp32 ---------------------
#define BM 128
#define BN 128
#define BK 16

__global__ __launch_bounds__(256) void sgemm_kernel(
    const float* __restrict__ A, const float* __restrict__ Bm,
    float* __restrict__ C, int Md, int Nd, int Kd)
{
    __shared__ float As[BK][BM + 4];   // transposed A tile, padded
    __shared__ float Bs[BK][BN];

    const int tid = threadIdx.x;
    const int tx = tid & 15;
    const int ty = tid >> 4;
    const int bm = blockIdx.y;
    const int bn = blockIdx.x;

    const float* Ablk = A + (size_t)bm * BM * Kd;
    const float* Bblk = Bm + (size_t)bn * BN;

    float acc[8][8];
#pragma unroll
    for (int i = 0; i < 8; i++)
#pragma unroll
        for (int j = 0; j < 8; j++) acc[i][j] = 0.0f;

    for (int kt = 0; kt < Kd; kt += BK) {
        // load A tile (128x16) transposed into As
#pragma unroll
        for (int u = 0; u < 2; u++) {
            int f = tid * 2 + u;          // 0..511
            int row = f >> 2;             // 0..127
            int c4 = (f & 3) * 4;         // 0,4,8,12
            float4 v = *(const float4*)(Ablk + (size_t)row * Kd + kt + c4);
            As[c4 + 0][row] = v.x;
            As[c4 + 1][row] = v.y;
            As[c4 + 2][row] = v.z;
            As[c4 + 3][row] = v.w;
        }
        // load B tile (16x128)
#pragma unroll
        for (int u = 0; u < 2; u++) {
            int f = tid * 2 + u;          // 0..511
            int row = f >> 5;             // 0..15
            int c4 = (f & 31) * 4;        // 0..124
            *(float4*)(&Bs[row][c4]) =
                *(const float4*)(Bblk + (size_t)(kt + row) * Nd + c4);
        }
        __syncthreads();

#pragma unroll
        for (int k = 0; k < BK; k++) {
            float a[8], b[8];
            *(float4*)(&a[0]) = *(const float4*)(&As[k][ty * 4]);
            *(float4*)(&a[4]) = *(const float4*)(&As[k][64 + ty * 4]);
            *(float4*)(&b[0]) = *(const float4*)(&Bs[k][tx * 4]);
            *(float4*)(&b[4]) = *(const float4*)(&Bs[k][64 + tx * 4]);
#pragma unroll
            for (int i = 0; i < 8; i++)
#pragma unroll
                for (int j = 0; j < 8; j++)
                    acc[i][j] = fmaf(a[i], b[j], acc[i][j]);
        }
        __syncthreads();
    }

#pragma unroll
    for (int i = 0; i < 8; i++) {
        int rloc = (i < 4) ? (ty * 4 + i) : (64 + ty * 4 + (i - 4));
        float* Crow = C + (size_t)(bm * BM + rloc) * Nd + bn * BN;
        float4 v0 = make_float4(acc[i][0], acc[i][1], acc[i][2], acc[i][3]);
        float4 v1 = make_float4(acc[i][4], acc[i][5], acc[i][6], acc[i][7]);
        *(float4*)(Crow + tx * 4) = v0;
        *(float4*)(Crow + 64 + tx * 4) = v1;
    }
}

// ---------------- RMSNorm + RoPE (per head-row of 64) -----------------------
// One warp handles one (token, head) row. lane holds d=lane and d=lane+32,
// which are exactly the rotary pair -> no shuffles needed for rotation.
__global__ __launch_bounds__(256) void rmsrope_kernel(
    float* __restrict__ X, const float* __restrict__ scale,
    const float* __restrict__ cosp, const float* __restrict__ sinp,
    int nheads, int nrows)
{
    int warp = (blockIdx.x * blockDim.x + threadIdx.x) >> 5;
    int lane = threadIdx.x & 31;
    if (warp >= nrows) return;

    int h = warp % nheads;
    int m = warp / nheads;            // b*S + s
    int s = m & (S_ - 1);

    float* xp = X + (size_t)m * (nheads * HD_) + h * HD_;
    float x0 = xp[lane];
    float x1 = xp[lane + 32];

    float ss = x0 * x0 + x1 * x1;
#pragma unroll
    for (int off = 16; off >= 1; off >>= 1)
        ss += __shfl_xor_sync(0xffffffffu, ss, off);

    float r = rsqrtf(ss * (1.0f / 64.0f) + 1e-6f);
    float n0 = x0 * r * scale[lane];
    float n1 = x1 * r * scale[lane + 32];

    float c0 = cosp[s * HD_ + lane];
    float c1 = cosp[s * HD_ + lane + 32];
    float s0 = sinp[s * HD_ + lane];
    float s1 = sinp[s * HD_ + lane + 32];

    xp[lane]      = n0 * c0 - n1 * s0;   // rot(d)    = -x[d+32]
    xp[lane + 32] = n1 * c1 + n0 * s1;   // rot(d+32) =  x[d]
}

// ---------------- Flash attention, causal, GQA ------------------------------
// Grid: (S/64, NH, B). 256 threads: (ty,tx) = 16x16.
// Thread owns q rows qi = ty*4+i (i<4), k cols kj = tx+16*j, d cols dd = tx+16*jd.
__global__ __launch_bounds__(256) void flash_kernel(
    const float* __restrict__ Q, const float* __restrict__ K,
    const float* __restrict__ V, float* __restrict__ O)
{
    extern __shared__ float sm[];
    float* Qs = sm;                 // 64*64
    float* Ks = sm + 4096;          // 64*65 (padded, conflict-free strided reads)
    float* Vs = sm + 4096 + 4160;   // 64*64
    float* Ps = Vs + 4096;          // 64*64

    const int tid = threadIdx.x;
    const int tx = tid & 15;
    const int ty = tid >> 4;
    const int qt = blockIdx.x;
    const int h  = blockIdx.y;
    const int b  = blockIdx.z;
    const int kvh = h >> 2;         // RATIO = 4

    const float* Qb = Q + ((size_t)(b * S_ + qt * 64)) * QCOLS + h * HD_;
    const float* Kb = K + ((size_t)b * S_) * KCOLS + kvh * HD_;
    const float* Vb = V + ((size_t)b * S_) * KCOLS + kvh * HD_;

    // load Q tile (scaled by 1/sqrt(HD))
#pragma unroll
    for (int u = 0; u < 4; u++) {
        int f = tid * 4 + u;             // 0..1023
        int row = f >> 4;
        int c = (f & 15) * 4;
        float4 v = *(const float4*)(Qb + (size_t)row * QCOLS + c);
        v.x *= 0.125f; v.y *= 0.125f; v.z *= 0.125f; v.w *= 0.125f;
        *(float4*)(&Qs[row * 64 + c]) = v;
    }

    float m_i[4], l_i[4], acc[4][4];
#pragma unroll
    for (int i = 0; i < 4; i++) {
        m_i[i] = -INFINITY;
        l_i[i] = 0.0f;
#pragma unroll
        for (int j = 0; j < 4; j++) acc[i][j] = 0.0f;
    }

    for (int kt = 0; kt <= qt; kt++) {
        // load K, V tiles
#pragma unroll
        for (int u = 0; u < 4; u++) {
            int f = tid * 4 + u;
            int row = f >> 4;
            int c = (f & 15) * 4;
            float4 kv = *(const float4*)(Kb + (size_t)(kt * 64 + row) * KCOLS + c);
            Ks[row * 65 + c + 0] = kv.x;
            Ks[row * 65 + c + 1] = kv.y;
            Ks[row * 65 + c + 2] = kv.z;
            Ks[row * 65 + c + 3] = kv.w;
            float4 vv = *(const float4*)(Vb + (size_t)(kt * 64 + row) * KCOLS + c);
            *(float4*)(&Vs[row * 64 + c]) = vv;
        }
        __syncthreads();

        // scores S = Q K^T (pre-scaled)
        float sreg[4][4];
#pragma unroll
        for (int i = 0; i < 4; i++)
#pragma unroll
            for (int j = 0; j < 4; j++) sreg[i][j] = 0.0f;

#pragma unroll 4
        for (int d = 0; d < 64; d++) {
            float qv[4], kvv[4];
#pragma unroll
            for (int i = 0; i < 4; i++) qv[i] = Qs[(ty * 4 + i) * 64 + d];
#pragma unroll
            for (int j = 0; j < 4; j++) kvv[j] = Ks[(tx + 16 * j) * 65 + d];
#pragma unroll
            for (int i = 0; i < 4; i++)
#pragma unroll
                for (int j = 0; j < 4; j++)
                    sreg[i][j] = fmaf(qv[i], kvv[j], sreg[i][j]);
        }

        // causal mask only needed on the diagonal tile
        if (kt == qt) {
#pragma unroll
            for (int i = 0; i < 4; i++)
#pragma unroll
                for (int j = 0; j < 4; j++)
                    if (tx + 16 * j > ty * 4 + i) sreg[i][j] = -1e30f;
        }

        // online softmax per q row (reduce across the 16 tx lanes)
#pragma unroll
        for (int i = 0; i < 4; i++) {
            float mx = fmaxf(fmaxf(sreg[i][0], sreg[i][1]),
                             fmaxf(sreg[i][2], sreg[i][3]));
#pragma unroll
            for (int off = 8; off >= 1; off >>= 1)
                mx = fmaxf(mx, __shfl_xor_sync(0xffffffffu, mx, off));
            float mnew = fmaxf(m_i[i], mx);
            float alpha = __expf(m_i[i] - mnew);
            float p[4];
            float rowsum = 0.0f;
#pragma unroll
            for (int j = 0; j < 4; j++) {
                p[j] = __expf(sreg[i][j] - mnew);
                rowsum += p[j];
            }
#pragma unroll
            for (int off = 8; off >= 1; off >>= 1)
                rowsum += __shfl_xor_sync(0xffffffffu, rowsum, off);
            l_i[i] = l_i[i] * alpha + rowsum;
            m_i[i] = mnew;
#pragma unroll
            for (int jd = 0; jd < 4; jd++) acc[i][jd] *= alpha;
#pragma unroll
            for (int j = 0; j < 4; j++)
                Ps[(ty * 4 + i) * 64 + tx + 16 * j] = p[j];
        }
        __syncthreads();

        // O += P @ V
#pragma unroll 4
        for (int k = 0; k < 64; k++) {
            float vv[4];
#pragma unroll
            for (int jd = 0; jd < 4; jd++) vv[jd] = Vs[k * 64 + tx + 16 * jd];
#pragma unroll
            for (int i = 0; i < 4; i++) {
                float pp = Ps[(ty * 4 + i) * 64 + k];
#pragma unroll
                for (int jd = 0; jd < 4; jd++)
                    acc[i][jd] = fmaf(pp, vv[jd], acc[i][jd]);
            }
        }
        __syncthreads();
    }

    // epilogue: normalize and store
#pragma unroll
    for (int i = 0; i < 4; i++) {
        float inv = 1.0f / l_i[i];
        size_t row = (size_t)(b * S_ + qt * 64 + ty * 4 + i) * QCOLS + h * HD_;
#pragma unroll
        for (int jd = 0; jd < 4; jd++)
            O[row + tx + 16 * jd] = acc[i][jd] * inv;
    }
}

// ---------------- launch ----------------------------------------------------
extern "C" void kernel_launch(void* const* d_in, const int* in_sizes, int n_in,
                              void* d_out, int out_size)
{
    const float* x       = (const float*)d_in[0];
    const float* wq      = (const float*)d_in[1];
    const float* wk      = (const float*)d_in[2];
    const float* wv      = (const float*)d_in[3];
    const float* wo      = (const float*)d_in[4];
    const float* q_scale = (const float*)d_in[5];
    const float* k_scale = (const float*)d_in[6];
    const float* cosp    = (const float*)d_in[7];
    const float* sinp    = (const float*)d_in[8];
    float* out = (float*)d_out;

    float *pq, *pk, *pv, *pao;
    cudaGetSymbolAddress((void**)&pq, g_q);
    cudaGetSymbolAddress((void**)&pk, g_k);
    cudaGetSymbolAddress((void**)&pv, g_v);
    cudaGetSymbolAddress((void**)&pao, g_ao);

    static bool attr_set = false;
    if (!attr_set) {
        cudaFuncSetAttribute(flash_kernel,
                             cudaFuncAttributeMaxDynamicSharedMemorySize,
                             (4096 + 4160 + 4096 + 4096) * sizeof(float));
        attr_set = true;
    }

    // QKV projections
    sgemm_kernel<<<dim3(QCOLS / BN, M_ / BM), 256>>>(x, wq, pq, M_, QCOLS, D_);
    sgemm_kernel<<<dim3(KCOLS / BN, M_ / BM), 256>>>(x, wk, pk, M_, KCOLS, D_);
    sgemm_kernel<<<dim3(KCOLS / BN, M_ / BM), 256>>>(x, wv, pv, M_, KCOLS, D_);

    // RMSNorm + RoPE in place
    {
        int qrows = M_ * NH_;
        rmsrope_kernel<<<(qrows * 32 + 255) / 256, 256>>>(pq, q_scale, cosp, sinp, NH_, qrows);
        int krows = M_ * NKV_;
        rmsrope_kernel<<<(krows * 32 + 255) / 256, 256>>>(pk, k_scale, cosp, sinp, NKV_, krows);
    }

    // causal GQA flash attention
    flash_kernel<<<dim3(S_ / 64, NH_, B_), 256,
                   (4096 + 4160 + 4096 + 4096) * sizeof(float)>>>(pq, pk, pv, pao);

    // output projection
    sgemm_kernel<<<dim3(D_ / BN, M_ / BM), 256>>>(pao, wo, out, M_, D_, D_);
}

// round 4
// speedup vs baseline: 1.4205x; 1.4205x over previous
#include <cuda_runtime.h>
#include <cuda_bf16.h>
#include <math.h>
#include <cstdint>

#define B_ 2
#define S_ 2048
#define D_ 2048
#define NH_ 32
#define NKV_ 8
#define HD_ 64
#define M_ (B_ * S_)            // 4096
#define QCOLS (NH_ * HD_)       // 2048
#define KCOLS (NKV_ * HD_)      // 512

// ---------------- scratch (device globals; no allocations allowed) ----------
__device__ float g_q[M_ * QCOLS];
__device__ float g_k[M_ * KCOLS];
__device__ float g_v[M_ * KCOLS];
__device__ float g_ao[M_ * QCOLS];
__device__ float g_xr[M_ * D_];          // tf32-rounded x
__device__ float g_wqT[QCOLS * D_];      // transposed + tf32-rounded weights [N,K]
__device__ float g_wkT[KCOLS * D_];
__device__ float g_wvT[KCOLS * D_];
__device__ float g_woT[D_ * QCOLS];

__device__ __forceinline__ float tf32r(float f) {
    uint32_t o;
    asm("cvt.rna.tf32.f32 %0, %1;" : "=r"(o) : "f"(f));
    return __uint_as_float(o);
}

__device__ __forceinline__ void cp16(uint32_t saddr, const float* gaddr) {
    asm volatile("cp.async.cg.shared.global [%0], [%1], 16;" :: "r"(saddr), "l"(gaddr) : "memory");
}
__device__ __forceinline__ uint32_t smem_u32(const void* p) {
    uint32_t a;
    asm("{ .reg .u64 t; cvta.to.shared.u64 t, %1; cvt.u32.u64 %0, t; }" : "=r"(a) : "l"(p));
    return a;
}

__device__ __forceinline__ void mma_tf32(float* c, uint32_t a0, uint32_t a1,
                                         uint32_t a2, uint32_t a3,
                                         uint32_t b0, uint32_t b1) {
    asm volatile(
        "mma.sync.aligned.m16n8k8.row.col.f32.tf32.tf32.f32 "
        "{%0,%1,%2,%3}, {%4,%5,%6,%7}, {%8,%9}, {%0,%1,%2,%3};"
        : "+f"(c[0]), "+f"(c[1]), "+f"(c[2]), "+f"(c[3])
        : "r"(a0), "r"(a1), "r"(a2), "r"(a3), "r"(b0), "r"(b1));
}

// ---------------- tf32 mma.sync GEMM ----------------------------------------
// C[M_,Nd] = A[M_,2048] @ BT[Nd,2048]^T.  CTA tile 128x128, BK=32, 2 stages.
// k-permutation: fragment k-col c at k-step kk <-> physical k = 4c + kk
// (applied identically to A and B; dot product invariant). This makes each
// thread's per-fragment data for all 4 k-steps one float4.
#define GBK 32
#define GSTR 36                          // row stride in floats (BK + 4 pad)
#define TILE_FLOATS (128 * GSTR)         // 4608
#define STAGE_FLOATS (2 * TILE_FLOATS)   // A tile + B tile
#define GEMM_SMEM_BYTES (2 * STAGE_FLOATS * 4)   // 73728

__device__ __forceinline__ void gemm_load_stage(
    uint32_t abase, uint32_t bbase,
    const float* __restrict__ Ab, const float* __restrict__ Bb, int chunk, int tid)
{
    const float* Ac = Ab + chunk * GBK;
    const float* Bc = Bb + chunk * GBK;
#pragma unroll
    for (int i = 0; i < 4; i++) {
        int idx = tid + 256 * i;
        int row = idx >> 3;
        int c4 = (idx & 7) * 4;
        cp16(abase + (row * GSTR + c4) * 4, Ac + (size_t)row * 2048 + c4);
        cp16(bbase + (row * GSTR + c4) * 4, Bc + (size_t)row * 2048 + c4);
    }
    asm volatile("cp.async.commit_group;" ::: "memory");
}

__global__ __launch_bounds__(256) void gemm_mma_kernel(
    const float* __restrict__ A,
    const float* __restrict__ BT0, float* __restrict__ C0,
    const float* __restrict__ BT1, float* __restrict__ C1, int Nd)
{
    extern __shared__ __align__(16) float sm[];
    const int tid = threadIdx.x;
    const int wid = tid >> 5;
    const int lane = tid & 31;
    const int gID = lane >> 2;
    const int tg = lane & 3;
    const int wm = (wid & 3) * 32;       // warp m-offset in tile
    const int wn = (wid >> 2) * 64;      // warp n-offset in tile
    const int bn = blockIdx.x, bm = blockIdx.y;

    const float* BT = blockIdx.z ? BT1 : BT0;
    float* C = blockIdx.z ? C1 : C0;

    const float* Ab = A + (size_t)bm * 128 * 2048;
    const float* Bb = BT + (size_t)bn * 128 * 2048;

    uint32_t sb = smem_u32(sm);
    uint32_t aoff[2], boff[2];
    aoff[0] = sb;
    boff[0] = sb + TILE_FLOATS * 4;
    aoff[1] = sb + STAGE_FLOATS * 4;
    boff[1] = aoff[1] + TILE_FLOATS * 4;

    float acc[2][8][4];
#pragma unroll
    for (int mt = 0; mt < 2; mt++)
#pragma unroll
        for (int j = 0; j < 8; j++)
#pragma unroll
            for (int q = 0; q < 4; q++) acc[mt][j][q] = 0.0f;

    gemm_load_stage(aoff[0], boff[0], Ab, Bb, 0, tid);

    for (int c = 0; c < 64; c++) {
        int s = c & 1;
        if (c < 63) {
            gemm_load_stage(aoff[s ^ 1], boff[s ^ 1], Ab, Bb, c + 1, tid);
            asm volatile("cp.async.wait_group 1;" ::: "memory");
        } else {
            asm volatile("cp.async.wait_group 0;" ::: "memory");
        }
        __syncthreads();

        const float* As = sm + s * STAGE_FLOATS;
        const float* Bs = As + TILE_FLOATS;

        // A fragments: [mt][4 float4], float4 spans the 4 k-steps
        float Af[2][4][4];
#pragma unroll
        for (int mt = 0; mt < 2; mt++) {
            int r0 = wm + mt * 16 + gID;
            *(float4*)Af[mt][0] = *(const float4*)&As[r0 * GSTR + 4 * tg];
            *(float4*)Af[mt][1] = *(const float4*)&As[(r0 + 8) * GSTR + 4 * tg];
            *(float4*)Af[mt][2] = *(const float4*)&As[r0 * GSTR + 4 * tg + 16];
            *(float4*)Af[mt][3] = *(const float4*)&As[(r0 + 8) * GSTR + 4 * tg + 16];
        }

#pragma unroll
        for (int j = 0; j < 8; j++) {
            int nr = wn + j * 8 + gID;
            float Bf0[4], Bf1[4];
            *(float4*)Bf0 = *(const float4*)&Bs[nr * GSTR + 4 * tg];
            *(float4*)Bf1 = *(const float4*)&Bs[nr * GSTR + 4 * tg + 16];
#pragma unroll
            for (int kk = 0; kk < 4; kk++) {
                uint32_t b0 = __float_as_uint(Bf0[kk]);
                uint32_t b1 = __float_as_uint(Bf1[kk]);
#pragma unroll
                for (int mt = 0; mt < 2; mt++) {
                    mma_tf32(acc[mt][j],
                             __float_as_uint(Af[mt][0][kk]),
                             __float_as_uint(Af[mt][1][kk]),
                             __float_as_uint(Af[mt][2][kk]),
                             __float_as_uint(Af[mt][3][kk]),
                             b0, b1);
                }
            }
        }
        __syncthreads();
    }

    // epilogue
#pragma unroll
    for (int mt = 0; mt < 2; mt++) {
        int row = bm * 128 + wm + mt * 16 + gID;
#pragma unroll
        for (int j = 0; j < 8; j++) {
            int col = bn * 128 + wn + j * 8 + 2 * tg;
            *(float2*)&C[(size_t)row * Nd + col] =
                make_float2(acc[mt][j][0], acc[mt][j][1]);
            *(float2*)&C[(size_t)(row + 8) * Nd + col] =
                make_float2(acc[mt][j][2], acc[mt][j][3]);
        }
    }
}

// ---------------- prep: tf32 rounding + weight transpose --------------------
__global__ __launch_bounds__(256) void round_x_kernel(const float* __restrict__ in,
                                                      float* __restrict__ out, int n4)
{
    int i = blockIdx.x * blockDim.x + threadIdx.x;
    if (i >= n4) return;
    float4 v = ((const float4*)in)[i];
    v.x = tf32r(v.x); v.y = tf32r(v.y); v.z = tf32r(v.z); v.w = tf32r(v.w);
    ((float4*)out)[i] = v;
}

__global__ __launch_bounds__(256) void transpose_round_kernel(
    const float* __restrict__ in, float* __restrict__ out, int K, int N)
{   // in [K,N] -> out [N,K], tf32-rounded
    __shared__ float t[32][33];
    int n0 = blockIdx.x * 32, k0 = blockIdx.y * 32;
    int tx = threadIdx.x, ty = threadIdx.y;
#pragma unroll
    for (int i = ty; i < 32; i += 8)
        t[i][tx] = in[(size_t)(k0 + i) * N + n0 + tx];
    __syncthreads();
#pragma unroll
    for (int i = ty; i < 32; i += 8)
        out[(size_t)(n0 + i) * K + k0 + tx] = tf32r(t[tx][i]);
}

// ---------------- RMSNorm + RoPE --------------------------------------------
__global__ __launch_bounds__(256) void rmsrope_kernel(
    float* __restrict__ X, const float* __restrict__ scale,
    const float* __restrict__ cosp, const float* __restrict__ sinp,
    int nheads, int nrows)
{
    int warp = (blockIdx.x * blockDim.x + threadIdx.x) >> 5;
    int lane = threadIdx.x & 31;
    if (warp >= nrows) return;

    int h = warp % nheads;
    int m = warp / nheads;
    int s = m & (S_ - 1);

    float* xp = X + (size_t)m * (nheads * HD_) + h * HD_;
    float x0 = xp[lane];
    float x1 = xp[lane + 32];

    float ss = x0 * x0 + x1 * x1;
#pragma unroll
    for (int off = 16; off >= 1; off >>= 1)
        ss += __shfl_xor_sync(0xffffffffu, ss, off);

    float r = rsqrtf(ss * (1.0f / 64.0f) + 1e-6f);
    float n0 = x0 * r * scale[lane];
    float n1 = x1 * r * scale[lane + 32];

    float c0 = cosp[s * HD_ + lane];
    float c1 = cosp[s * HD_ + lane + 32];
    float s0 = sinp[s * HD_ + lane];
    float s1 = sinp[s * HD_ + lane + 32];

    xp[lane]      = n0 * c0 - n1 * s0;
    xp[lane + 32] = n1 * c1 + n0 * s1;
}

// ---------------- Flash attention, causal, GQA ------------------------------
__global__ __launch_bounds__(256) void flash_kernel(
    const float* __restrict__ Q, const float* __restrict__ K,
    const float* __restrict__ V, float* __restrict__ O)
{
    extern __shared__ float smf[];
    float* Qs = smf;
    float* Ks = smf + 4096;
    float* Vs = smf + 4096 + 4160;
    float* Ps = Vs + 4096;

    const int tid = threadIdx.x;
    const int tx = tid & 15;
    const int ty = tid >> 4;
    const int qt = blockIdx.x;
    const int h  = blockIdx.y;
    const int b  = blockIdx.z;
    const int kvh = h >> 2;

    const float* Qb = Q + ((size_t)(b * S_ + qt * 64)) * QCOLS + h * HD_;
    const float* Kb = K + ((size_t)b * S_) * KCOLS + kvh * HD_;
    const float* Vb = V + ((size_t)b * S_) * KCOLS + kvh * HD_;

#pragma unroll
    for (int u = 0; u < 4; u++) {
        int f = tid * 4 + u;
        int row = f >> 4;
        int c = (f & 15) * 4;
        float4 v = *(const float4*)(Qb + (size_t)row * QCOLS + c);
        v.x *= 0.125f; v.y *= 0.125f; v.z *= 0.125f; v.w *= 0.125f;
        *(float4*)(&Qs[row * 64 + c]) = v;
    }

    float m_i[4], l_i[4], acc[4][4];
#pragma unroll
    for (int i = 0; i < 4; i++) {
        m_i[i] = -INFINITY;
        l_i[i] = 0.0f;
#pragma unroll
        for (int j = 0; j < 4; j++) acc[i][j] = 0.0f;
    }

    for (int kt = 0; kt <= qt; kt++) {
#pragma unroll
        for (int u = 0; u < 4; u++) {
            int f = tid * 4 + u;
            int row = f >> 4;
            int c = (f & 15) * 4;
            float4 kv = *(const float4*)(Kb + (size_t)(kt * 64 + row) * KCOLS + c);
            Ks[row * 65 + c + 0] = kv.x;
            Ks[row * 65 + c + 1] = kv.y;
            Ks[row * 65 + c + 2] = kv.z;
            Ks[row * 65 + c + 3] = kv.w;
            float4 vv = *(const float4*)(Vb + (size_t)(kt * 64 + row) * KCOLS + c);
            *(float4*)(&Vs[row * 64 + c]) = vv;
        }
        __syncthreads();

        float sreg[4][4];
#pragma unroll
        for (int i = 0; i < 4; i++)
#pragma unroll
            for (int j = 0; j < 4; j++) sreg[i][j] = 0.0f;

#pragma unroll 4
        for (int d = 0; d < 64; d++) {
            float qv[4], kvv[4];
#pragma unroll
            for (int i = 0; i < 4; i++) qv[i] = Qs[(ty * 4 + i) * 64 + d];
#pragma unroll
            for (int j = 0; j < 4; j++) kvv[j] = Ks[(tx + 16 * j) * 65 + d];
#pragma unroll
            for (int i = 0; i < 4; i++)
#pragma unroll
                for (int j = 0; j < 4; j++)
                    sreg[i][j] = fmaf(qv[i], kvv[j], sreg[i][j]);
        }

        if (kt == qt) {
#pragma unroll
            for (int i = 0; i < 4; i++)
#pragma unroll
                for (int j = 0; j < 4; j++)
                    if (tx + 16 * j > ty * 4 + i) sreg[i][j] = -1e30f;
        }

#pragma unroll
        for (int i = 0; i < 4; i++) {
            float mx = fmaxf(fmaxf(sreg[i][0], sreg[i][1]),
                             fmaxf(sreg[i][2], sreg[i][3]));
#pragma unroll
            for (int off = 8; off >= 1; off >>= 1)
                mx = fmaxf(mx, __shfl_xor_sync(0xffffffffu, mx, off));
            float mnew = fmaxf(m_i[i], mx);
            float alpha = __expf(m_i[i] - mnew);
            float p[4];
            float rowsum = 0.0f;
#pragma unroll
            for (int j = 0; j < 4; j++) {
                p[j] = __expf(sreg[i][j] - mnew);
                rowsum += p[j];
            }
#pragma unroll
            for (int off = 8; off >= 1; off >>= 1)
                rowsum += __shfl_xor_sync(0xffffffffu, rowsum, off);
            l_i[i] = l_i[i] * alpha + rowsum;
            m_i[i] = mnew;
#pragma unroll
            for (int jd = 0; jd < 4; jd++) acc[i][jd] *= alpha;
#pragma unroll
            for (int j = 0; j < 4; j++)
                Ps[(ty * 4 + i) * 64 + tx + 16 * j] = p[j];
        }
        __syncthreads();

#pragma unroll 4
        for (int k = 0; k < 64; k++) {
            float vv[4];
#pragma unroll
            for (int jd = 0; jd < 4; jd++) vv[jd] = Vs[k * 64 + tx + 16 * jd];
#pragma unroll
            for (int i = 0; i < 4; i++) {
                float pp = Ps[(ty * 4 + i) * 64 + k];
#pragma unroll
                for (int jd = 0; jd < 4; jd++)
                    acc[i][jd] = fmaf(pp, vv[jd], acc[i][jd]);
            }
        }
        __syncthreads();
    }

#pragma unroll
    for (int i = 0; i < 4; i++) {
        float inv = 1.0f / l_i[i];
        size_t row = (size_t)(b * S_ + qt * 64 + ty * 4 + i) * QCOLS + h * HD_;
#pragma unroll
        for (int jd = 0; jd < 4; jd++)
            O[row + tx + 16 * jd] = tf32r(acc[i][jd] * inv);   // rounded for O GEMM
    }
}

// ---------------- launch ----------------------------------------------------
extern "C" void kernel_launch(void* const* d_in, const int* in_sizes, int n_in,
                              void* d_out, int out_size)
{
    const float* x       = (const float*)d_in[0];
    const float* wq      = (const float*)d_in[1];
    const float* wk      = (const float*)d_in[2];
    const float* wv      = (const float*)d_in[3];
    const float* wo      = (const float*)d_in[4];
    const float* q_scale = (const float*)d_in[5];
    const float* k_scale = (const float*)d_in[6];
    const float* cosp    = (const float*)d_in[7];
    const float* sinp    = (const float*)d_in[8];
    float* out = (float*)d_out;

    float *pq, *pk, *pv, *pao, *pxr, *pwqT, *pwkT, *pwvT, *pwoT;
    cudaGetSymbolAddress((void**)&pq, g_q);
    cudaGetSymbolAddress((void**)&pk, g_k);
    cudaGetSymbolAddress((void**)&pv, g_v);
    cudaGetSymbolAddress((void**)&pao, g_ao);
    cudaGetSymbolAddress((void**)&pxr, g_xr);
    cudaGetSymbolAddress((void**)&pwqT, g_wqT);
    cudaGetSymbolAddress((void**)&pwkT, g_wkT);
    cudaGetSymbolAddress((void**)&pwvT, g_wvT);
    cudaGetSymbolAddress((void**)&pwoT, g_woT);

    cudaFuncSetAttribute(flash_kernel,
                         cudaFuncAttributeMaxDynamicSharedMemorySize,
                         (4096 + 4160 + 4096 + 4096) * sizeof(float));
    cudaFuncSetAttribute(gemm_mma_kernel,
                         cudaFuncAttributeMaxDynamicSharedMemorySize,
                         GEMM_SMEM_BYTES);

    // prep: tf32-round x, transpose+round weights to [N,K]
    {
        int n4 = M_ * D_ / 4;
        round_x_kernel<<<(n4 + 255) / 256, 256>>>(x, pxr, n4);
        transpose_round_kernel<<<dim3(QCOLS / 32, D_ / 32), dim3(32, 8)>>>(wq, pwqT, D_, QCOLS);
        transpose_round_kernel<<<dim3(KCOLS / 32, D_ / 32), dim3(32, 8)>>>(wk, pwkT, D_, KCOLS);
        transpose_round_kernel<<<dim3(KCOLS / 32, D_ / 32), dim3(32, 8)>>>(wv, pwvT, D_, KCOLS);
        transpose_round_kernel<<<dim3(D_ / 32, QCOLS / 32), dim3(32, 8)>>>(wo, pwoT, QCOLS, D_);
    }

    // projections on tf32 mma.sync
    gemm_mma_kernel<<<dim3(QCOLS / 128, M_ / 128, 1), 256, GEMM_SMEM_BYTES>>>(
        pxr, pwqT, pq, pwqT, pq, QCOLS);
    gemm_mma_kernel<<<dim3(KCOLS / 128, M_ / 128, 2), 256, GEMM_SMEM_BYTES>>>(
        pxr, pwkT, pk, pwvT, pv, KCOLS);

    // RMSNorm + RoPE in place
    {
        int qrows = M_ * NH_;
        rmsrope_kernel<<<(qrows * 32 + 255) / 256, 256>>>(pq, q_scale, cosp, sinp, NH_, qrows);
        int krows = M_ * NKV_;
        rmsrope_kernel<<<(krows * 32 + 255) / 256, 256>>>(pk, k_scale, cosp, sinp, NKV_, krows);
    }

    // causal GQA flash attention
    flash_kernel<<<dim3(S_ / 64, NH_, B_), 256,
                   (4096 + 4160 + 4096 + 4096) * sizeof(float)>>>(pq, pk, pv, pao);

    // output projection
    gemm_mma_kernel<<<dim3(D_ / 128, M_ / 128, 1), 256, GEMM_SMEM_BYTES>>>(
        pao, pwoT, out, pwoT, out, D_);
}

// round 5
// speedup vs baseline: 2.3496x; 1.6541x over previous
#include <cuda_runtime.h>
#include <cuda_bf16.h>
#include <math.h>
#include <cstdint>

#define B_ 2
#define S_ 2048
#define D_ 2048
#define NH_ 32
#define NKV_ 8
#define HD_ 64
#define M_ (B_ * S_)            // 4096
#define QCOLS (NH_ * HD_)       // 2048
#define KCOLS (NKV_ * HD_)      // 512

// ---------------- scratch (device globals; no allocations allowed) ----------
__device__ float g_q[M_ * QCOLS];
__device__ float g_k[M_ * KCOLS];
__device__ float g_v[M_ * KCOLS];
__device__ float g_vT[B_ * NKV_ * HD_ * S_];   // V transposed: [(b*8+kvh)*64+d][s]
__device__ float g_ao[M_ * QCOLS];
__device__ float g_xr[M_ * D_];          // tf32-rounded x
__device__ float g_wqT[QCOLS * D_];      // transposed + tf32-rounded weights [N,K]
__device__ float g_wkT[KCOLS * D_];
__device__ float g_wvT[KCOLS * D_];
__device__ float g_woT[D_ * QCOLS];

__device__ __forceinline__ float tf32r(float f) {
    uint32_t o;
    asm("cvt.rna.tf32.f32 %0, %1;" : "=r"(o) : "f"(f));
    return __uint_as_float(o);
}

__device__ __forceinline__ void cp16(uint32_t saddr, const float* gaddr) {
    asm volatile("cp.async.cg.shared.global [%0], [%1], 16;" :: "r"(saddr), "l"(gaddr) : "memory");
}
__device__ __forceinline__ uint32_t smem_u32(const void* p) {
    uint32_t a;
    asm("{ .reg .u64 t; cvta.to.shared.u64 t, %1; cvt.u32.u64 %0, t; }" : "=r"(a) : "l"(p));
    return a;
}

__device__ __forceinline__ void mma_tf32(float* c, uint32_t a0, uint32_t a1,
                                         uint32_t a2, uint32_t a3,
                                         uint32_t b0, uint32_t b1) {
    asm volatile(
        "mma.sync.aligned.m16n8k8.row.col.f32.tf32.tf32.f32 "
        "{%0,%1,%2,%3}, {%4,%5,%6,%7}, {%8,%9}, {%0,%1,%2,%3};"
        : "+f"(c[0]), "+f"(c[1]), "+f"(c[2]), "+f"(c[3])
        : "r"(a0), "r"(a1), "r"(a2), "r"(a3), "r"(b0), "r"(b1));
}
#define FU(x) __float_as_uint(x)

// ---------------- tf32 mma.sync GEMM (unchanged from round 4) ---------------
#define GBK 32
#define GSTR 36
#define TILE_FLOATS (128 * GSTR)
#define STAGE_FLOATS (2 * TILE_FLOATS)
#define GEMM_SMEM_BYTES (2 * STAGE_FLOATS * 4)

__device__ __forceinline__ void gemm_load_stage(
    uint32_t abase, uint32_t bbase,
    const float* __restrict__ Ab, const float* __restrict__ Bb, int chunk, int tid)
{
    const float* Ac = Ab + chunk * GBK;
    const float* Bc = Bb + chunk * GBK;
#pragma unroll
    for (int i = 0; i < 4; i++) {
        int idx = tid + 256 * i;
        int row = idx >> 3;
        int c4 = (idx & 7) * 4;
        cp16(abase + (row * GSTR + c4) * 4, Ac + (size_t)row * 2048 + c4);
        cp16(bbase + (row * GSTR + c4) * 4, Bc + (size_t)row * 2048 + c4);
    }
    asm volatile("cp.async.commit_group;" ::: "memory");
}

__global__ __launch_bounds__(256) void gemm_mma_kernel(
    const float* __restrict__ A,
    const float* __restrict__ BT0, float* __restrict__ C0,
    const float* __restrict__ BT1, float* __restrict__ C1, int Nd)
{
    extern __shared__ __align__(16) float sm[];
    const int tid = threadIdx.x;
    const int wid = tid >> 5;
    const int lane = tid & 31;
    const int gID = lane >> 2;
    const int tg = lane & 3;
    const int wm = (wid & 3) * 32;
    const int wn = (wid >> 2) * 64;
    const int bn = blockIdx.x, bm = blockIdx.y;

    const float* BT = blockIdx.z ? BT1 : BT0;
    float* C = blockIdx.z ? C1 : C0;

    const float* Ab = A + (size_t)bm * 128 * 2048;
    const float* Bb = BT + (size_t)bn * 128 * 2048;

    uint32_t sb = smem_u32(sm);
    uint32_t aoff[2], boff[2];
    aoff[0] = sb;
    boff[0] = sb + TILE_FLOATS * 4;
    aoff[1] = sb + STAGE_FLOATS * 4;
    boff[1] = aoff[1] + TILE_FLOATS * 4;

    float acc[2][8][4];
#pragma unroll
    for (int mt = 0; mt < 2; mt++)
#pragma unroll
        for (int j = 0; j < 8; j++)
#pragma unroll
            for (int q = 0; q < 4; q++) acc[mt][j][q] = 0.0f;

    gemm_load_stage(aoff[0], boff[0], Ab, Bb, 0, tid);

    for (int c = 0; c < 64; c++) {
        int s = c & 1;
        if (c < 63) {
            gemm_load_stage(aoff[s ^ 1], boff[s ^ 1], Ab, Bb, c + 1, tid);
            asm volatile("cp.async.wait_group 1;" ::: "memory");
        } else {
            asm volatile("cp.async.wait_group 0;" ::: "memory");
        }
        __syncthreads();

        const float* As = sm + s * STAGE_FLOATS;
        const float* Bs = As + TILE_FLOATS;

        float Af[2][4][4];
#pragma unroll
        for (int mt = 0; mt < 2; mt++) {
            int r0 = wm + mt * 16 + gID;
            *(float4*)Af[mt][0] = *(const float4*)&As[r0 * GSTR + 4 * tg];
            *(float4*)Af[mt][1] = *(const float4*)&As[(r0 + 8) * GSTR + 4 * tg];
            *(float4*)Af[mt][2] = *(const float4*)&As[r0 * GSTR + 4 * tg + 16];
            *(float4*)Af[mt][3] = *(const float4*)&As[(r0 + 8) * GSTR + 4 * tg + 16];
        }

#pragma unroll
        for (int j = 0; j < 8; j++) {
            int nr = wn + j * 8 + gID;
            float Bf0[4], Bf1[4];
            *(float4*)Bf0 = *(const float4*)&Bs[nr * GSTR + 4 * tg];
            *(float4*)Bf1 = *(const float4*)&Bs[nr * GSTR + 4 * tg + 16];
#pragma unroll
            for (int kk = 0; kk < 4; kk++) {
                uint32_t b0 = FU(Bf0[kk]);
                uint32_t b1 = FU(Bf1[kk]);
#pragma unroll
                for (int mt = 0; mt < 2; mt++) {
                    mma_tf32(acc[mt][j],
                             FU(Af[mt][0][kk]), FU(Af[mt][1][kk]),
                             FU(Af[mt][2][kk]), FU(Af[mt][3][kk]),
                             b0, b1);
                }
            }
        }
        __syncthreads();
    }

#pragma unroll
    for (int mt = 0; mt < 2; mt++) {
        int row = bm * 128 + wm + mt * 16 + gID;
#pragma unroll
        for (int j = 0; j < 8; j++) {
            int col = bn * 128 + wn + j * 8 + 2 * tg;
            *(float2*)&C[(size_t)row * Nd + col] =
                make_float2(acc[mt][j][0], acc[mt][j][1]);
            *(float2*)&C[(size_t)(row + 8) * Nd + col] =
                make_float2(acc[mt][j][2], acc[mt][j][3]);
        }
    }
}

// ---------------- prep kernels ----------------------------------------------
__global__ __launch_bounds__(256) void round_x_kernel(const float* __restrict__ in,
                                                      float* __restrict__ out, int n4)
{
    int i = blockIdx.x * blockDim.x + threadIdx.x;
    if (i >= n4) return;
    float4 v = ((const float4*)in)[i];
    v.x = tf32r(v.x); v.y = tf32r(v.y); v.z = tf32r(v.z); v.w = tf32r(v.w);
    ((float4*)out)[i] = v;
}

__global__ __launch_bounds__(256) void transpose_round_kernel(
    const float* __restrict__ in, float* __restrict__ out, int K, int N)
{   // in [K,N] -> out [N,K], tf32-rounded
    __shared__ float t[32][33];
    int n0 = blockIdx.x * 32, k0 = blockIdx.y * 32;
    int tx = threadIdx.x, ty = threadIdx.y;
#pragma unroll
    for (int i = ty; i < 32; i += 8)
        t[i][tx] = in[(size_t)(k0 + i) * N + n0 + tx];
    __syncthreads();
#pragma unroll
    for (int i = ty; i < 32; i += 8)
        out[(size_t)(n0 + i) * K + k0 + tx] = tf32r(t[tx][i]);
}

// V [b*S+s][kvh*64+d] -> VT [(b*8+kvh)*64+d][s], tf32-rounded
__global__ __launch_bounds__(256) void transpose_v_kernel(
    const float* __restrict__ V, float* __restrict__ VT)
{
    __shared__ float t[32][33];
    int s0 = blockIdx.x * 32;
    int d0 = blockIdx.y * 32;
    int bh = blockIdx.z;               // b*8+kvh
    int b = bh >> 3, kvh = bh & 7;
    int tx = threadIdx.x, ty = threadIdx.y;
#pragma unroll
    for (int i = ty; i < 32; i += 8)
        t[i][tx] = V[(size_t)(b * S_ + s0 + i) * KCOLS + kvh * 64 + d0 + tx];
    __syncthreads();
#pragma unroll
    for (int i = ty; i < 32; i += 8)
        VT[(size_t)(bh * 64 + d0 + i) * S_ + s0 + tx] = tf32r(t[tx][i]);
}

// ---------------- RMSNorm + RoPE (outputs tf32-rounded) ---------------------
__global__ __launch_bounds__(256) void rmsrope_kernel(
    float* __restrict__ X, const float* __restrict__ scale,
    const float* __restrict__ cosp, const float* __restrict__ sinp,
    int nheads, int nrows)
{
    int warp = (blockIdx.x * blockDim.x + threadIdx.x) >> 5;
    int lane = threadIdx.x & 31;
    if (warp >= nrows) return;

    int h = warp % nheads;
    int m = warp / nheads;
    int s = m & (S_ - 1);

    float* xp = X + (size_t)m * (nheads * HD_) + h * HD_;
    float x0 = xp[lane];
    float x1 = xp[lane + 32];

    float ss = x0 * x0 + x1 * x1;
#pragma unroll
    for (int off = 16; off >= 1; off >>= 1)
        ss += __shfl_xor_sync(0xffffffffu, ss, off);

    float r = rsqrtf(ss * (1.0f / 64.0f) + 1e-6f);
    float n0 = x0 * r * scale[lane];
    float n1 = x1 * r * scale[lane + 32];

    float c0 = cosp[s * HD_ + lane];
    float c1 = cosp[s * HD_ + lane + 32];
    float s0 = sinp[s * HD_ + lane];
    float s1 = sinp[s * HD_ + lane + 32];

    xp[lane]      = tf32r(n0 * c0 - n1 * s0);
    xp[lane + 32] = tf32r(n1 * c1 + n0 * s1);
}

// ---------------- Flash attention on tf32 mma.sync --------------------------
// 128 q-rows per CTA, 8 warps x 16 rows, 64-wide KV tiles, double-buffered.
// k-permutation: fragment col c at step kk <-> physical k = 8c + kk.
#define FQT 128
#define FSTR 68
#define FK_OFF(s)  ((s) * 64 * FSTR)
#define FV_OFF(s)  ((2 + (s)) * 64 * FSTR)
#define FP_OFF     (4 * 64 * FSTR)
#define FLASH_SMEM_BYTES ((4 * 64 * FSTR + FQT * FSTR) * 4)   // 104448

__global__ __launch_bounds__(256, 1) void flash_mma_kernel(
    const float* __restrict__ Q, const float* __restrict__ K,
    const float* __restrict__ VT, float* __restrict__ O)
{
    extern __shared__ __align__(16) float smf[];
    uint32_t sb = smem_u32(smf);
    const int tid = threadIdx.x;
    const int w = tid >> 5;
    const int lane = tid & 31;
    const int gID = lane >> 2;
    const int tg = lane & 3;
    const int qt = blockIdx.x;
    const int h = blockIdx.y;
    const int b = blockIdx.z;
    const int kvh = h >> 2;
    const int qbase = qt * FQT;

    const float* Qb = Q + ((size_t)(b * S_ + qbase)) * QCOLS + h * HD_;
    const float* Kb = K + ((size_t)b * S_) * KCOLS + kvh * HD_;
    const float* VTb = VT + ((size_t)(b * NKV_ + kvh)) * HD_ * S_;

    // Q fragments in registers (rows r0, r0+8; cols via k-permute), scaled 1/8
    const int r0 = 16 * w + gID;
    float Qa0[8], Qa1[8], Qa2[8], Qa3[8];
    {
        const float* q0 = Qb + (size_t)r0 * QCOLS;
        const float* q1 = Qb + (size_t)(r0 + 8) * QCOLS;
        *(float4*)&Qa0[0] = *(const float4*)&q0[8 * tg];
        *(float4*)&Qa0[4] = *(const float4*)&q0[8 * tg + 4];
        *(float4*)&Qa1[0] = *(const float4*)&q1[8 * tg];
        *(float4*)&Qa1[4] = *(const float4*)&q1[8 * tg + 4];
        *(float4*)&Qa2[0] = *(const float4*)&q0[8 * tg + 32];
        *(float4*)&Qa2[4] = *(const float4*)&q0[8 * tg + 36];
        *(float4*)&Qa3[0] = *(const float4*)&q1[8 * tg + 32];
        *(float4*)&Qa3[4] = *(const float4*)&q1[8 * tg + 36];
#pragma unroll
        for (int kk = 0; kk < 8; kk++) {
            Qa0[kk] *= 0.125f; Qa1[kk] *= 0.125f;
            Qa2[kk] *= 0.125f; Qa3[kk] *= 0.125f;
        }
    }

    float Oacc[8][4];
#pragma unroll
    for (int j = 0; j < 8; j++)
#pragma unroll
        for (int q = 0; q < 4; q++) Oacc[j][q] = 0.0f;
    float m0 = -INFINITY, m1 = -INFINITY, l0 = 0.0f, l1 = 0.0f;

    const int ntiles = 2 * qt + 2;

    // tile loader: K rows [64 x 64] + VT rows [64 d x 64 s]
    auto load_tile = [&](int kt, int s) {
        uint32_t kbase = sb + FK_OFF(s) * 4;
        uint32_t vbase = sb + FV_OFF(s) * 4;
        const float* Ksrc = Kb + (size_t)(kt * 64) * KCOLS;
        const float* Vsrc = VTb + kt * 64;
#pragma unroll
        for (int i = 0; i < 4; i++) {
            int idx = tid + 256 * i;          // 0..1023
            int row = idx >> 4;
            int c4 = (idx & 15) * 4;
            cp16(kbase + (row * FSTR + c4) * 4, Ksrc + (size_t)row * KCOLS + c4);
            cp16(vbase + (row * FSTR + c4) * 4, Vsrc + (size_t)row * S_ + c4);
        }
        asm volatile("cp.async.commit_group;" ::: "memory");
    };

    load_tile(0, 0);

    for (int kt = 0; kt < ntiles; kt++) {
        int s = kt & 1;
        if (kt + 1 < ntiles) {
            load_tile(kt + 1, s ^ 1);
            asm volatile("cp.async.wait_group 1;" ::: "memory");
        } else {
            asm volatile("cp.async.wait_group 0;" ::: "memory");
        }
        __syncthreads();

        int ktbase = kt * 64;
        bool skip = (ktbase > qbase + 16 * w + 15);   // warp fully masked
        if (!skip) {
            const float* Ks = smf + FK_OFF(s);
            const float* Vs = smf + FV_OFF(s);
            float* Ps = smf + FP_OFF;

            // S = Q K^T
            float sreg[8][4];
#pragma unroll
            for (int j = 0; j < 8; j++)
#pragma unroll
                for (int q = 0; q < 4; q++) sreg[j][q] = 0.0f;

#pragma unroll
            for (int j = 0; j < 8; j++) {
                float Kb0[8], Kb1[8];
                const float* kr = &Ks[(8 * j + gID) * FSTR];
                *(float4*)&Kb0[0] = *(const float4*)&kr[8 * tg];
                *(float4*)&Kb0[4] = *(const float4*)&kr[8 * tg + 4];
                *(float4*)&Kb1[0] = *(const float4*)&kr[8 * tg + 32];
                *(float4*)&Kb1[4] = *(const float4*)&kr[8 * tg + 36];
#pragma unroll
                for (int kk = 0; kk < 8; kk++)
                    mma_tf32(sreg[j], FU(Qa0[kk]), FU(Qa1[kk]),
                             FU(Qa2[kk]), FU(Qa3[kk]),
                             FU(Kb0[kk]), FU(Kb1[kk]));
            }

            // causal mask (warp-uniform trigger)
            if (ktbase + 63 > qbase + 16 * w) {
                int qg0 = qbase + 16 * w + gID;
                int qg1 = qg0 + 8;
#pragma unroll
                for (int j = 0; j < 8; j++) {
                    int c0 = ktbase + 8 * j + 2 * tg;
                    if (c0 > qg0)     sreg[j][0] = -1e30f;
                    if (c0 + 1 > qg0) sreg[j][1] = -1e30f;
                    if (c0 > qg1)     sreg[j][2] = -1e30f;
                    if (c0 + 1 > qg1) sreg[j][3] = -1e30f;
                }
            }

            // online softmax (rows gID / gID+8; reduce across quad lanes)
            float mx0 = -INFINITY, mx1 = -INFINITY;
#pragma unroll
            for (int j = 0; j < 8; j++) {
                mx0 = fmaxf(mx0, fmaxf(sreg[j][0], sreg[j][1]));
                mx1 = fmaxf(mx1, fmaxf(sreg[j][2], sreg[j][3]));
            }
            mx0 = fmaxf(mx0, __shfl_xor_sync(0xffffffffu, mx0, 1));
            mx0 = fmaxf(mx0, __shfl_xor_sync(0xffffffffu, mx0, 2));
            mx1 = fmaxf(mx1, __shfl_xor_sync(0xffffffffu, mx1, 1));
            mx1 = fmaxf(mx1, __shfl_xor_sync(0xffffffffu, mx1, 2));

            float mn0 = fmaxf(m0, mx0), mn1 = fmaxf(m1, mx1);
            float al0 = __expf(m0 - mn0), al1 = __expf(m1 - mn1);

            float sum0 = 0.0f, sum1 = 0.0f;
            float* pr0 = &Ps[r0 * FSTR];
            float* pr1 = &Ps[(r0 + 8) * FSTR];
#pragma unroll
            for (int j = 0; j < 8; j++) {
                float p0 = tf32r(__expf(sreg[j][0] - mn0));
                float p1 = tf32r(__expf(sreg[j][1] - mn0));
                float p2 = tf32r(__expf(sreg[j][2] - mn1));
                float p3 = tf32r(__expf(sreg[j][3] - mn1));
                sum0 += p0 + p1;
                sum1 += p2 + p3;
                *(float2*)&pr0[8 * j + 2 * tg] = make_float2(p0, p1);
                *(float2*)&pr1[8 * j + 2 * tg] = make_float2(p2, p3);
            }
            sum0 += __shfl_xor_sync(0xffffffffu, sum0, 1);
            sum0 += __shfl_xor_sync(0xffffffffu, sum0, 2);
            sum1 += __shfl_xor_sync(0xffffffffu, sum1, 1);
            sum1 += __shfl_xor_sync(0xffffffffu, sum1, 2);

            l0 = l0 * al0 + sum0;
            l1 = l1 * al1 + sum1;
            m0 = mn0; m1 = mn1;
#pragma unroll
            for (int j = 0; j < 8; j++) {
                Oacc[j][0] *= al0; Oacc[j][1] *= al0;
                Oacc[j][2] *= al1; Oacc[j][3] *= al1;
            }
            __syncwarp();

            // O += P V   (A = P from smem, B = V^T fragments)
            float Pa0[8], Pa1[8], Pa2[8], Pa3[8];
            *(float4*)&Pa0[0] = *(const float4*)&pr0[8 * tg];
            *(float4*)&Pa0[4] = *(const float4*)&pr0[8 * tg + 4];
            *(float4*)&Pa1[0] = *(const float4*)&pr1[8 * tg];
            *(float4*)&Pa1[4] = *(const float4*)&pr1[8 * tg + 4];
            *(float4*)&Pa2[0] = *(const float4*)&pr0[8 * tg + 32];
            *(float4*)&Pa2[4] = *(const float4*)&pr0[8 * tg + 36];
            *(float4*)&Pa3[0] = *(const float4*)&pr1[8 * tg + 32];
            *(float4*)&Pa3[4] = *(const float4*)&pr1[8 * tg + 36];

#pragma unroll
            for (int j = 0; j < 8; j++) {
                float Vb0[8], Vb1[8];
                const float* vr = &Vs[(8 * j + gID) * FSTR];
                *(float4*)&Vb0[0] = *(const float4*)&vr[8 * tg];
                *(float4*)&Vb0[4] = *(const float4*)&vr[8 * tg + 4];
                *(float4*)&Vb1[0] = *(const float4*)&vr[8 * tg + 32];
                *(float4*)&Vb1[4] = *(const float4*)&vr[8 * tg + 36];
#pragma unroll
                for (int kk = 0; kk < 8; kk++)
                    mma_tf32(Oacc[j], FU(Pa0[kk]), FU(Pa1[kk]),
                             FU(Pa2[kk]), FU(Pa3[kk]),
                             FU(Vb0[kk]), FU(Vb1[kk]));
            }
        }
        __syncthreads();   // protect buffers before next prefetch overwrite
    }

    // epilogue
    float inv0 = 1.0f / l0, inv1 = 1.0f / l1;
    float* O0 = O + ((size_t)(b * S_ + qbase + r0)) * QCOLS + h * HD_;
    float* O1 = O + ((size_t)(b * S_ + qbase + r0 + 8)) * QCOLS + h * HD_;
#pragma unroll
    for (int j = 0; j < 8; j++) {
        int c = 8 * j + 2 * tg;
        *(float2*)&O0[c] = make_float2(tf32r(Oacc[j][0] * inv0),
                                       tf32r(Oacc[j][1] * inv0));
        *(float2*)&O1[c] = make_float2(tf32r(Oacc[j][2] * inv1),
                                       tf32r(Oacc[j][3] * inv1));
    }
}

// ---------------- launch ----------------------------------------------------
extern "C" void kernel_launch(void* const* d_in, const int* in_sizes, int n_in,
                              void* d_out, int out_size)
{
    const float* x       = (const float*)d_in[0];
    const float* wq      = (const float*)d_in[1];
    const float* wk      = (const float*)d_in[2];
    const float* wv      = (const float*)d_in[3];
    const float* wo      = (const float*)d_in[4];
    const float* q_scale = (const float*)d_in[5];
    const float* k_scale = (const float*)d_in[6];
    const float* cosp    = (const float*)d_in[7];
    const float* sinp    = (const float*)d_in[8];
    float* out = (float*)d_out;

    float *pq, *pk, *pv, *pvT, *pao, *pxr, *pwqT, *pwkT, *pwvT, *pwoT;
    cudaGetSymbolAddress((void**)&pq, g_q);
    cudaGetSymbolAddress((void**)&pk, g_k);
    cudaGetSymbolAddress((void**)&pv, g_v);
    cudaGetSymbolAddress((void**)&pvT, g_vT);
    cudaGetSymbolAddress((void**)&pao, g_ao);
    cudaGetSymbolAddress((void**)&pxr, g_xr);
    cudaGetSymbolAddress((void**)&pwqT, g_wqT);
    cudaGetSymbolAddress((void**)&pwkT, g_wkT);
    cudaGetSymbolAddress((void**)&pwvT, g_wvT);
    cudaGetSymbolAddress((void**)&pwoT, g_woT);

    cudaFuncSetAttribute(flash_mma_kernel,
                         cudaFuncAttributeMaxDynamicSharedMemorySize,
                         FLASH_SMEM_BYTES);
    cudaFuncSetAttribute(gemm_mma_kernel,
                         cudaFuncAttributeMaxDynamicSharedMemorySize,
                         GEMM_SMEM_BYTES);

    // prep: tf32-round x, transpose+round weights to [N,K]
    {
        int n4 = M_ * D_ / 4;
        round_x_kernel<<<(n4 + 255) / 256, 256>>>(x, pxr, n4);
        transpose_round_kernel<<<dim3(QCOLS / 32, D_ / 32), dim3(32, 8)>>>(wq, pwqT, D_, QCOLS);
        transpose_round_kernel<<<dim3(KCOLS / 32, D_ / 32), dim3(32, 8)>>>(wk, pwkT, D_, KCOLS);
        transpose_round_kernel<<<dim3(KCOLS / 32, D_ / 32), dim3(32, 8)>>>(wv, pwvT, D_, KCOLS);
        transpose_round_kernel<<<dim3(D_ / 32, QCOLS / 32), dim3(32, 8)>>>(wo, pwoT, QCOLS, D_);
    }

    // projections on tf32 mma.sync
    gemm_mma_kernel<<<dim3(QCOLS / 128, M_ / 128, 1), 256, GEMM_SMEM_BYTES>>>(
        pxr, pwqT, pq, pwqT, pq, QCOLS);
    gemm_mma_kernel<<<dim3(KCOLS / 128, M_ / 128, 2), 256, GEMM_SMEM_BYTES>>>(
        pxr, pwkT, pk, pwvT, pv, KCOLS);

    // RMSNorm + RoPE in place (tf32-rounded outputs)
    {
        int qrows = M_ * NH_;
        rmsrope_kernel<<<(qrows * 32 + 255) / 256, 256>>>(pq, q_scale, cosp, sinp, NH_, qrows);
        int krows = M_ * NKV_;
        rmsrope_kernel<<<(krows * 32 + 255) / 256, 256>>>(pk, k_scale, cosp, sinp, NKV_, krows);
    }

    // V transpose (+tf32 round) for mma-friendly layout
    transpose_v_kernel<<<dim3(S_ / 32, HD_ / 32, B_ * NKV_), dim3(32, 8)>>>(pv, pvT);

    // causal GQA flash attention on tensor cores
    flash_mma_kernel<<<dim3(S_ / FQT, NH_, B_), 256, FLASH_SMEM_BYTES>>>(
        pq, pk, pvT, pao);

    // output projection
    gemm_mma_kernel<<<dim3(D_ / 128, M_ / 128, 1), 256, GEMM_SMEM_BYTES>>>(
        pao, pwoT, out, pwoT, out, D_);
}